// round 1
// baseline (speedup 1.0000x reference)
#include <cuda_runtime.h>
#include <cuda_bf16.h>

// Problem constants
#define BB   32
#define NN   2048
#define DD   65
#define HH   64
#define DSQ  (DD*DD)        // 4225
#define NCHUNK1 16          // gram: 2048/128
#define ROWS1   128
#define NCHUNK3 32          // out:  2048/64
#define ROWS3   64

// Scratch (no allocations allowed)
__device__ float g_Gpart[BB * NCHUNK1 * DSQ];   // partial Gram matrices (~8.6 MB)
__device__ float g_A[DSQ];                      // Wq^T Wk
__device__ float g_M[BB * DSQ];                 // per-batch 65x65 combined matrix

// ---------------------------------------------------------------------------
// Kernel 0: A[i][j] = sum_h Wq[h][i] * Wk[h][j]   (65x65, batch-independent)
// ---------------------------------------------------------------------------
__global__ void k_A(const float* __restrict__ Wq, const float* __restrict__ Wk) {
    int t = blockIdx.x * blockDim.x + threadIdx.x;
    if (t >= DSQ) return;
    int i = t / DD, j = t - i * DD;
    float s = 0.f;
#pragma unroll
    for (int h = 0; h < HH; ++h)
        s = fmaf(Wq[h * DD + i], Wk[h * DD + j], s);
    g_A[t] = s;
}

// ---------------------------------------------------------------------------
// Kernel 1: partial Gram G_b += x_chunk^T x_chunk  (per batch b, 128-row chunk)
// grid = (16, 32), block = 256 (16x16), 5x5 register tile -> covers 80x80 >= 65x65
// ---------------------------------------------------------------------------
__global__ void k_gram(const float* __restrict__ x) {
    __shared__ float xs[ROWS1 * 80];   // pitch 80, cols 65..79 zeroed
    const int b = blockIdx.y, c = blockIdx.x;
    const float* xp = x + ((size_t)b * NN + (size_t)c * ROWS1) * DD;
    const int tid = threadIdx.x;

    for (int idx = tid; idx < ROWS1 * 80; idx += 256) {
        int r = idx / 80, col = idx - r * 80;
        xs[idx] = (col < DD) ? xp[r * DD + col] : 0.f;
    }
    __syncthreads();

    const int ty = tid >> 4, tx = tid & 15;
    float acc[5][5];
#pragma unroll
    for (int u = 0; u < 5; ++u)
#pragma unroll
        for (int v = 0; v < 5; ++v) acc[u][v] = 0.f;

#pragma unroll 4
    for (int k = 0; k < ROWS1; ++k) {
        float a[5], bb[5];
#pragma unroll
        for (int u = 0; u < 5; ++u) {
            a[u]  = xs[k * 80 + ty + 16 * u];
            bb[u] = xs[k * 80 + tx + 16 * u];
        }
#pragma unroll
        for (int u = 0; u < 5; ++u)
#pragma unroll
            for (int v = 0; v < 5; ++v)
                acc[u][v] = fmaf(a[u], bb[v], acc[u][v]);
    }

    float* gp = g_Gpart + ((size_t)(b * NCHUNK1 + c)) * DSQ;
#pragma unroll
    for (int u = 0; u < 5; ++u) {
        int i = ty + 16 * u;
        if (i >= DD) continue;
#pragma unroll
        for (int v = 0; v < 5; ++v) {
            int j = tx + 16 * v;
            if (j < DD) gp[i * DD + j] = acc[u][v];
        }
    }
}

// ---------------------------------------------------------------------------
// Kernel 2: per batch — reduce partial Grams, then M_b = A * G_b * Wv^T
// grid = 32, block = 256. Two shared buffers reused across phases.
// ---------------------------------------------------------------------------
__global__ void k_finalize(const float* __restrict__ Wv) {
    __shared__ float S1[DSQ];  // G, then T = A*G
    __shared__ float S2[DSQ];  // A, then Wv
    const int b = blockIdx.x;
    const int tid = threadIdx.x;

    for (int idx = tid; idx < DSQ; idx += 256) {
        float s = 0.f;
        const float* gp = g_Gpart + (size_t)b * NCHUNK1 * DSQ + idx;
#pragma unroll
        for (int c = 0; c < NCHUNK1; ++c) s += gp[c * DSQ];
        S1[idx] = s;
        S2[idx] = g_A[idx];
    }
    __syncthreads();

    // phase 1: T[i][j] = sum_k A[i][k] * G[k][j]  (into registers)
    float tloc[17];
    int cnt = 0;
    for (int idx = tid; idx < DSQ; idx += 256) {
        int i = idx / DD, j = idx - i * DD;
        float s = 0.f;
#pragma unroll
        for (int k = 0; k < DD; ++k)
            s = fmaf(S2[i * DD + k], S1[k * DD + j], s);
        tloc[cnt++] = s;
    }
    __syncthreads();

    cnt = 0;
    for (int idx = tid; idx < DSQ; idx += 256) {
        S1[idx] = tloc[cnt++];
        S2[idx] = Wv[idx];
    }
    __syncthreads();

    // phase 2: M[i][j] = sum_k T[i][k] * Wv[j][k]   (Wv^T[k][j] = Wv[j][k])
    for (int idx = tid; idx < DSQ; idx += 256) {
        int i = idx / DD, j = idx - i * DD;
        float s = 0.f;
#pragma unroll
        for (int k = 0; k < DD; ++k)
            s = fmaf(S1[i * DD + k], S2[j * DD + k], s);
        g_M[b * DSQ + idx] = s;
    }
}

// ---------------------------------------------------------------------------
// Kernel 3: out_chunk = x_chunk * M_b   (64 rows x 65 cols per block)
// grid = (32, 32), block = 256 (16x16), 4x5 register tile
// ---------------------------------------------------------------------------
__global__ void k_out(const float* __restrict__ x, float* __restrict__ out) {
    __shared__ float xs[ROWS3 * DD];   // linear, contiguous copy
    __shared__ float Ms[DD * 80];      // pitch 80
    const int b = blockIdx.y, c = blockIdx.x;
    const float* xp = x + ((size_t)b * NN + (size_t)c * ROWS3) * DD;
    float* op = out + ((size_t)b * NN + (size_t)c * ROWS3) * DD;
    const int tid = threadIdx.x;

    for (int idx = tid; idx < ROWS3 * DD; idx += 256) xs[idx] = xp[idx];
    const float* Mg = g_M + (size_t)b * DSQ;
    for (int idx = tid; idx < DD * 80; idx += 256) {
        int r = idx / 80, col = idx - r * 80;
        Ms[idx] = (col < DD) ? Mg[r * DD + col] : 0.f;
    }
    __syncthreads();

    const int ty = tid >> 4, tx = tid & 15;
    float acc[4][5];
#pragma unroll
    for (int u = 0; u < 4; ++u)
#pragma unroll
        for (int v = 0; v < 5; ++v) acc[u][v] = 0.f;

#pragma unroll 5
    for (int k = 0; k < DD; ++k) {
        float a[4], mv[5];
#pragma unroll
        for (int u = 0; u < 4; ++u) a[u] = xs[(ty + 16 * u) * DD + k];
#pragma unroll
        for (int v = 0; v < 5; ++v) mv[v] = Ms[k * 80 + tx + 16 * v];
#pragma unroll
        for (int u = 0; u < 4; ++u)
#pragma unroll
            for (int v = 0; v < 5; ++v)
                acc[u][v] = fmaf(a[u], mv[v], acc[u][v]);
    }

#pragma unroll
    for (int u = 0; u < 4; ++u) {
        int r = ty + 16 * u;
#pragma unroll
        for (int v = 0; v < 5; ++v) {
            int col = tx + 16 * v;
            if (col < DD) op[r * DD + col] = acc[u][v];
        }
    }
}

// ---------------------------------------------------------------------------
extern "C" void kernel_launch(void* const* d_in, const int* in_sizes, int n_in,
                              void* d_out, int out_size) {
    const float* x  = (const float*)d_in[0];   // [32, 2048, 65]
    const float* Wq = (const float*)d_in[1];   // [64, 65]
    const float* Wk = (const float*)d_in[2];   // [64, 65]
    const float* Wv = (const float*)d_in[3];   // [65, 65]
    float* out = (float*)d_out;                // [32, 2048, 65]

    k_A<<<(DSQ + 255) / 256, 256>>>(Wq, Wk);
    k_gram<<<dim3(NCHUNK1, BB), 256>>>(x);
    k_finalize<<<BB, 256>>>(Wv);
    k_out<<<dim3(NCHUNK3, BB), 256>>>(x, out);
}

// round 3
// speedup vs baseline: 1.0652x; 1.0652x over previous
#include <cuda_runtime.h>

// Problem constants
#define BB   32
#define NN   2048
#define DD   65
#define HH   64
#define DSQ  (DD*DD)        // 4225
#define GCH  64             // gram chunk rows
#define NGC  (NN/GCH)       // 32
#define OCH  64             // out chunk rows
#define NOC  (NN/OCH)       // 32

typedef unsigned long long ull;

// Scratch (no allocations allowed)
__device__ float g_Gpart[BB * NGC * DSQ];   // partial Gram matrices (~17.3 MB)
__device__ float g_G[BB * DSQ];             // reduced Gram
__device__ float g_A[DSQ];                  // Wq^T Wk
__device__ float g_M[BB * DSQ];             // per-batch 65x65 combined matrix

// ---- packed fp32x2 helpers (Blackwell FFMA2 path) ----
__device__ __forceinline__ ull pack2(float x) {
    ull d; unsigned u = __float_as_uint(x);
    asm("mov.b64 %0, {%1, %1};" : "=l"(d) : "r"(u));
    return d;
}
__device__ __forceinline__ ull fma2(ull a, ull b, ull c) {
    ull d;
    asm("fma.rn.f32x2 %0, %1, %2, %3;" : "=l"(d) : "l"(a), "l"(b), "l"(c));
    return d;
}
__device__ __forceinline__ void unpack2(ull d, float& lo, float& hi) {
    unsigned a, b;
    asm("mov.b64 {%0, %1}, %2;" : "=r"(a), "=r"(b) : "l"(d));
    lo = __uint_as_float(a); hi = __uint_as_float(b);
}

// ---------------------------------------------------------------------------
// Kernel 0: A[i][j] = sum_h Wq[h][i] * Wk[h][j]
// ---------------------------------------------------------------------------
__global__ void k_A(const float* __restrict__ Wq, const float* __restrict__ Wk) {
    int t = blockIdx.x * blockDim.x + threadIdx.x;
    if (t >= DSQ) return;
    int i = t / DD, j = t - i * DD;
    float s = 0.f;
#pragma unroll
    for (int h = 0; h < HH; ++h)
        s = fmaf(Wq[h * DD + i], Wk[h * DD + j], s);
    g_A[t] = s;
}

// ---------------------------------------------------------------------------
// Kernel 1: partial Gram for a 64-row chunk. FFMA2 inner loop.
// Output tile: rows i = ty+16u (u<5, covers 80>=65), col pairs p (j=2p,2p+1).
// Single smem buffer xs[64][80]: scalar broadcast reads (rows side) AND
// aligned ull pair reads (cols side). Cols 65..79 zeroed.
// ---------------------------------------------------------------------------
__global__ void __launch_bounds__(256) k_gram(const float* __restrict__ x) {
    __shared__ __align__(16) float xs[GCH * 80];

    const int b = blockIdx.y, c = blockIdx.x;
    const float* xp = x + ((size_t)b * NN + (size_t)c * GCH) * DD;
    const int tid = threadIdx.x;

    for (int idx = tid; idx < GCH * DD; idx += 256) {
        int r = idx / DD, col = idx - r * DD;
        xs[r * 80 + col] = xp[idx];
    }
    for (int idx = tid; idx < GCH * 15; idx += 256) {
        int r = idx / 15, col = 65 + idx % 15;
        xs[r * 80 + col] = 0.f;
    }
    __syncthreads();

    const int ty = tid >> 4, tx = tid & 15;
    // pair indices: p0 in 0..15, p1 in 16..31, p2 covers pair 32 (tx==0), else dead pad pair 33
    const int p0 = tx, p1 = 16 + tx, p2 = (tx == 0) ? 32 : 33;

    ull acc[5][3];
#pragma unroll
    for (int u = 0; u < 5; ++u)
#pragma unroll
        for (int v = 0; v < 3; ++v) acc[u][v] = 0ull;

#pragma unroll 4
    for (int k = 0; k < GCH; ++k) {
        const float* xr = xs + k * 80;
        const ull* xd = (const ull*)xr;          // 40 aligned pairs per row
        ull b0 = xd[p0], b1 = xd[p1], b2 = xd[p2];
#pragma unroll
        for (int u = 0; u < 5; ++u) {
            ull ad = pack2(xr[ty + 16 * u]);
            acc[u][0] = fma2(ad, b0, acc[u][0]);
            acc[u][1] = fma2(ad, b1, acc[u][1]);
            acc[u][2] = fma2(ad, b2, acc[u][2]);
        }
    }

    float* gp = g_Gpart + (size_t)(b * NGC + c) * DSQ;
    const int pv[3] = {p0, p1, p2};
#pragma unroll
    for (int u = 0; u < 5; ++u) {
        int i = ty + 16 * u;
        if (i >= DD) continue;
#pragma unroll
        for (int v = 0; v < 3; ++v) {
            int j0 = 2 * pv[v];
            float lo, hi;
            unpack2(acc[u][v], lo, hi);
            if (j0     < DD) gp[i * DD + j0]     = lo;
            if (j0 + 1 < DD) gp[i * DD + j0 + 1] = hi;
        }
    }
}

// ---------------------------------------------------------------------------
// Kernel 2: reduce 32 partial Grams -> g_G.  grid (17, 32), block 256.
// ---------------------------------------------------------------------------
__global__ void k_reduce() {
    const int b = blockIdx.y;
    int idx = blockIdx.x * 256 + threadIdx.x;
    if (idx >= DSQ) return;
    const float* gp = g_Gpart + (size_t)b * NGC * DSQ + idx;
    float s0 = 0.f, s1 = 0.f, s2 = 0.f, s3 = 0.f;
#pragma unroll
    for (int c = 0; c < NGC; c += 4) {
        s0 += gp[(c + 0) * DSQ];
        s1 += gp[(c + 1) * DSQ];
        s2 += gp[(c + 2) * DSQ];
        s3 += gp[(c + 3) * DSQ];
    }
    g_G[b * DSQ + idx] = (s0 + s1) + (s2 + s3);
}

// ---------------------------------------------------------------------------
// Kernel 3: M_b = A * G_b * Wv^T   (per batch, 65x65 matmuls in smem)
// ---------------------------------------------------------------------------
__global__ void k_mid(const float* __restrict__ Wv) {
    __shared__ float S1[DSQ];
    __shared__ float S2[DSQ];
    const int b = blockIdx.x;
    const int tid = threadIdx.x;

    for (int idx = tid; idx < DSQ; idx += 256) {
        S1[idx] = g_G[b * DSQ + idx];
        S2[idx] = g_A[idx];
    }
    __syncthreads();

    float tloc[17];
    int cnt = 0;
    for (int idx = tid; idx < DSQ; idx += 256) {
        int i = idx / DD, j = idx - i * DD;
        float s = 0.f;
#pragma unroll
        for (int k = 0; k < DD; ++k)
            s = fmaf(S2[i * DD + k], S1[k * DD + j], s);
        tloc[cnt++] = s;
    }
    __syncthreads();

    cnt = 0;
    for (int idx = tid; idx < DSQ; idx += 256) {
        S1[idx] = tloc[cnt++];
        S2[idx] = Wv[idx];
    }
    __syncthreads();

    for (int idx = tid; idx < DSQ; idx += 256) {
        int i = idx / DD, j = idx - i * DD;
        float s = 0.f;
#pragma unroll
        for (int k = 0; k < DD; ++k)
            s = fmaf(S1[i * DD + k], S2[j * DD + k], s);
        g_M[b * DSQ + idx] = s;
    }
}

// ---------------------------------------------------------------------------
// Kernel 4: out_chunk = x_chunk * M_b.  FFMA2 inner loop.
// Ms[65][68]: contiguous rows of M, cols 65..67 zeroed, pitch even -> ull pairs.
// xs[64][66]: x rows (scalar reads only).
// ---------------------------------------------------------------------------
__global__ void __launch_bounds__(256) k_out(const float* __restrict__ x,
                                             float* __restrict__ out) {
    __shared__ __align__(16) float Ms[DD * 68];
    __shared__ __align__(16) float xs[OCH * 66];

    const int b = blockIdx.y, c = blockIdx.x;
    const float* xp = x + ((size_t)b * NN + (size_t)c * OCH) * DD;
    float* op = out + ((size_t)b * NN + (size_t)c * OCH) * DD;
    const int tid = threadIdx.x;

    const float* Mg = g_M + (size_t)b * DSQ;
    for (int idx = tid; idx < DSQ; idx += 256) {
        int k = idx / DD, j = idx - k * DD;
        Ms[k * 68 + j] = Mg[idx];
    }
    for (int idx = tid; idx < DD * 3; idx += 256) {
        int k = idx / 3, t = idx % 3;
        Ms[k * 68 + 65 + t] = 0.f;
    }
    for (int idx = tid; idx < OCH * DD; idx += 256) {
        int r = idx / DD, k = idx - r * DD;
        xs[r * 66 + k] = xp[idx];
    }
    __syncthreads();

    const int ty = tid >> 4, tx = tid & 15;
    const int p0 = tx, p1 = 16 + tx, p2 = (tx == 0) ? 32 : 33;  // pair 33 = pad

    ull acc[4][3];
#pragma unroll
    for (int u = 0; u < 4; ++u)
#pragma unroll
        for (int v = 0; v < 3; ++v) acc[u][v] = 0ull;

#pragma unroll 5
    for (int k = 0; k < DD; ++k) {
        const ull* mr = (const ull*)(Ms + k * 68);   // 34 aligned pairs
        ull m0 = mr[p0], m1 = mr[p1], m2 = mr[p2];
#pragma unroll
        for (int u = 0; u < 4; ++u) {
            ull ad = pack2(xs[(ty + 16 * u) * 66 + k]);
            acc[u][0] = fma2(ad, m0, acc[u][0]);
            acc[u][1] = fma2(ad, m1, acc[u][1]);
            acc[u][2] = fma2(ad, m2, acc[u][2]);
        }
    }

    const int pv[3] = {p0, p1, p2};
#pragma unroll
    for (int u = 0; u < 4; ++u) {
        int r = ty + 16 * u;
#pragma unroll
        for (int v = 0; v < 3; ++v) {
            int j0 = 2 * pv[v];
            float lo, hi;
            unpack2(acc[u][v], lo, hi);
            if (j0     < DD) op[r * DD + j0]     = lo;
            if (j0 + 1 < DD) op[r * DD + j0 + 1] = hi;
        }
    }
}

// ---------------------------------------------------------------------------
extern "C" void kernel_launch(void* const* d_in, const int* in_sizes, int n_in,
                              void* d_out, int out_size) {
    const float* x  = (const float*)d_in[0];   // [32, 2048, 65]
    const float* Wq = (const float*)d_in[1];   // [64, 65]
    const float* Wk = (const float*)d_in[2];   // [64, 65]
    const float* Wv = (const float*)d_in[3];   // [65, 65]
    float* out = (float*)d_out;                // [32, 2048, 65]

    k_A<<<(DSQ + 255) / 256, 256>>>(Wq, Wk);
    k_gram<<<dim3(NGC, BB), 256>>>(x);
    k_reduce<<<dim3(17, BB), 256>>>();
    k_mid<<<BB, 256>>>(Wv);
    k_out<<<dim3(NOC, BB), 256>>>(x, out);
}

// round 4
// speedup vs baseline: 1.1391x; 1.0694x over previous
#include <cuda_runtime.h>

// Problem constants
#define BB   32
#define NN   2048
#define DD   65
#define HH   64
#define DSQ  (DD*DD)        // 4225
#define GSUB 64             // gram sub-chunk rows (smem tile)
#define NSUB 4              // sub-chunks accumulated per block
#define GCH  (GSUB*NSUB)    // 256 rows per gram block
#define NGC  (NN/GCH)       // 8 partials per batch
#define OCH  64             // out chunk rows
#define NOC  (NN/OCH)       // 32
#define MMROWS 13           // k_mm65 rows per block (5*13 = 65)

typedef unsigned long long ull;

// Scratch (no allocations allowed)
__device__ float g_Gpart[BB * NGC * DSQ];   // partial Gram matrices (~4.3 MB)
__device__ float g_G[BB * DSQ];             // reduced Gram
__device__ float g_A[DSQ];                  // Wq^T Wk
__device__ float g_T[BB * DSQ];             // T = A * G
__device__ float g_M[BB * DSQ];             // M = T * Wv^T

// ---- packed fp32x2 helpers (Blackwell FFMA2 path) ----
__device__ __forceinline__ ull pack2(float x) {
    ull d; unsigned u = __float_as_uint(x);
    asm("mov.b64 %0, {%1, %1};" : "=l"(d) : "r"(u));
    return d;
}
__device__ __forceinline__ ull fma2(ull a, ull b, ull c) {
    ull d;
    asm("fma.rn.f32x2 %0, %1, %2, %3;" : "=l"(d) : "l"(a), "l"(b), "l"(c));
    return d;
}
__device__ __forceinline__ void unpack2(ull d, float& lo, float& hi) {
    unsigned a, b;
    asm("mov.b64 {%0, %1}, %2;" : "=r"(a), "=r"(b) : "l"(d));
    lo = __uint_as_float(a); hi = __uint_as_float(b);
}

// ---------------------------------------------------------------------------
// Kernel 0: A[i][j] = sum_h Wq[h][i] * Wk[h][j]
// ---------------------------------------------------------------------------
__global__ void k_A(const float* __restrict__ Wq, const float* __restrict__ Wk) {
    int t = blockIdx.x * blockDim.x + threadIdx.x;
    if (t >= DSQ) return;
    int i = t / DD, j = t - i * DD;
    float s = 0.f;
#pragma unroll
    for (int h = 0; h < HH; ++h)
        s = fmaf(Wq[h * DD + i], Wk[h * DD + j], s);
    g_A[t] = s;
}

// ---------------------------------------------------------------------------
// Kernel 1: partial Gram for a 256-row chunk (4 x 64-row smem tiles,
// register accumulation across tiles). FFMA2 inner loop.
// Output tile per thread: rows i = ty+16u (u<5), col pairs p0/p1/p2.
// ---------------------------------------------------------------------------
__global__ void __launch_bounds__(256) k_gram(const float* __restrict__ x) {
    __shared__ __align__(16) float xs[GSUB * 80];

    const int b = blockIdx.y, c = blockIdx.x;
    const int tid = threadIdx.x;
    const int ty = tid >> 4, tx = tid & 15;
    const int p0 = tx, p1 = 16 + tx, p2 = (tx == 0) ? 32 : 33;  // pair 33 = pad

    // zero pads once (cols 65..79 never rewritten)
    for (int idx = tid; idx < GSUB * 15; idx += 256) {
        int r = idx / 15, col = 65 + idx % 15;
        xs[r * 80 + col] = 0.f;
    }

    ull acc[5][3];
#pragma unroll
    for (int u = 0; u < 5; ++u)
#pragma unroll
        for (int v = 0; v < 3; ++v) acc[u][v] = 0ull;

    for (int s = 0; s < NSUB; ++s) {
        const float* xp = x + ((size_t)b * NN + (size_t)c * GCH + (size_t)s * GSUB) * DD;
        __syncthreads();
        for (int idx = tid; idx < GSUB * DD; idx += 256) {
            int r = idx / DD, col = idx - r * DD;
            xs[r * 80 + col] = xp[idx];
        }
        __syncthreads();

#pragma unroll 4
        for (int k = 0; k < GSUB; ++k) {
            const float* xr = xs + k * 80;
            const ull* xd = (const ull*)xr;          // 40 aligned pairs per row
            ull b0 = xd[p0], b1 = xd[p1], b2 = xd[p2];
#pragma unroll
            for (int u = 0; u < 5; ++u) {
                ull ad = pack2(xr[ty + 16 * u]);
                acc[u][0] = fma2(ad, b0, acc[u][0]);
                acc[u][1] = fma2(ad, b1, acc[u][1]);
                acc[u][2] = fma2(ad, b2, acc[u][2]);
            }
        }
    }

    float* gp = g_Gpart + (size_t)(b * NGC + c) * DSQ;
    const int pv[3] = {p0, p1, p2};
#pragma unroll
    for (int u = 0; u < 5; ++u) {
        int i = ty + 16 * u;
        if (i >= DD) continue;
#pragma unroll
        for (int v = 0; v < 3; ++v) {
            int j0 = 2 * pv[v];
            float lo, hi;
            unpack2(acc[u][v], lo, hi);
            if (j0     < DD) gp[i * DD + j0]     = lo;
            if (j0 + 1 < DD) gp[i * DD + j0 + 1] = hi;
        }
    }
}

// ---------------------------------------------------------------------------
// Kernel 2: reduce 8 partial Grams -> g_G.  grid (17, 32), block 256.
// ---------------------------------------------------------------------------
__global__ void k_reduce() {
    const int b = blockIdx.y;
    int idx = blockIdx.x * 256 + threadIdx.x;
    if (idx >= DSQ) return;
    const float* gp = g_Gpart + (size_t)b * NGC * DSQ + idx;
    float s0 = 0.f, s1 = 0.f, s2 = 0.f, s3 = 0.f;
#pragma unroll
    for (int c = 0; c < NGC; c += 4) {
        s0 += gp[(c + 0) * DSQ];
        s1 += gp[(c + 1) * DSQ];
        s2 += gp[(c + 2) * DSQ];
        s3 += gp[(c + 3) * DSQ];
    }
    g_G[b * DSQ + idx] = (s0 + s1) + (s2 + s3);
}

// ---------------------------------------------------------------------------
// Kernel 3: generic 65x65 row-row matmul: C[i][j] = sum_k P[i][k] * Q[j][k].
// Phase 1: P=A (stride 0), Q=G_b (symmetric -> row form OK), C=T_b.
// Phase 2: P=T_b, Q=Wv (stride 0), C=M_b.
// grid (5 tiles, 32 batches), block 256, 13 rows per tile. Static loops only.
// ---------------------------------------------------------------------------
__global__ void __launch_bounds__(256) k_mm65(const float* __restrict__ P, int pStr,
                                              const float* __restrict__ Q, int qStr,
                                              float* __restrict__ C) {
    __shared__ float Ps[MMROWS * DD];
    __shared__ float Qs[DSQ];
    const int b = blockIdx.y, t0 = blockIdx.x;
    const int tid = threadIdx.x;
    const float* Pb = P + (size_t)b * pStr + (size_t)t0 * MMROWS * DD;
    const float* Qb = Q + (size_t)b * qStr;
    float* Cb = C + (size_t)b * DSQ + (size_t)t0 * MMROWS * DD;

    for (int idx = tid; idx < MMROWS * DD; idx += 256) Ps[idx] = Pb[idx];
    for (int idx = tid; idx < DSQ; idx += 256)         Qs[idx] = Qb[idx];
    __syncthreads();

#pragma unroll
    for (int m = 0; m < 4; ++m) {
        int idx = tid + 256 * m;
        if (idx < MMROWS * DD) {
            int i = idx / DD, j = idx - i * DD;
            float s = 0.f;
#pragma unroll
            for (int k = 0; k < DD; ++k)
                s = fmaf(Ps[i * DD + k], Qs[j * DD + k], s);
            Cb[idx] = s;
        }
    }
}

// ---------------------------------------------------------------------------
// Kernel 4: out_chunk = x_chunk * M_b.  FFMA2 inner loop.
// ---------------------------------------------------------------------------
__global__ void __launch_bounds__(256) k_out(const float* __restrict__ x,
                                             float* __restrict__ out) {
    __shared__ __align__(16) float Ms[DD * 68];
    __shared__ __align__(16) float xs[OCH * 66];

    const int b = blockIdx.y, c = blockIdx.x;
    const float* xp = x + ((size_t)b * NN + (size_t)c * OCH) * DD;
    float* op = out + ((size_t)b * NN + (size_t)c * OCH) * DD;
    const int tid = threadIdx.x;

    const float* Mg = g_M + (size_t)b * DSQ;
    for (int idx = tid; idx < DSQ; idx += 256) {
        int k = idx / DD, j = idx - k * DD;
        Ms[k * 68 + j] = Mg[idx];
    }
    for (int idx = tid; idx < DD * 3; idx += 256) {
        int k = idx / 3, t = idx % 3;
        Ms[k * 68 + 65 + t] = 0.f;
    }
    for (int idx = tid; idx < OCH * DD; idx += 256) {
        int r = idx / DD, k = idx - r * DD;
        xs[r * 66 + k] = xp[idx];
    }
    __syncthreads();

    const int ty = tid >> 4, tx = tid & 15;
    const int p0 = tx, p1 = 16 + tx, p2 = (tx == 0) ? 32 : 33;  // pair 33 = pad

    ull acc[4][3];
#pragma unroll
    for (int u = 0; u < 4; ++u)
#pragma unroll
        for (int v = 0; v < 3; ++v) acc[u][v] = 0ull;

#pragma unroll 5
    for (int k = 0; k < DD; ++k) {
        const ull* mr = (const ull*)(Ms + k * 68);   // 34 aligned pairs
        ull m0 = mr[p0], m1 = mr[p1], m2 = mr[p2];
#pragma unroll
        for (int u = 0; u < 4; ++u) {
            ull ad = pack2(xs[(ty + 16 * u) * 66 + k]);
            acc[u][0] = fma2(ad, m0, acc[u][0]);
            acc[u][1] = fma2(ad, m1, acc[u][1]);
            acc[u][2] = fma2(ad, m2, acc[u][2]);
        }
    }

    const int pv[3] = {p0, p1, p2};
#pragma unroll
    for (int u = 0; u < 4; ++u) {
        int r = ty + 16 * u;
#pragma unroll
        for (int v = 0; v < 3; ++v) {
            int j0 = 2 * pv[v];
            float lo, hi;
            unpack2(acc[u][v], lo, hi);
            if (j0     < DD) op[r * DD + j0]     = lo;
            if (j0 + 1 < DD) op[r * DD + j0 + 1] = hi;
        }
    }
}

// ---------------------------------------------------------------------------
extern "C" void kernel_launch(void* const* d_in, const int* in_sizes, int n_in,
                              void* d_out, int out_size) {
    const float* x  = (const float*)d_in[0];   // [32, 2048, 65]
    const float* Wq = (const float*)d_in[1];   // [64, 65]
    const float* Wk = (const float*)d_in[2];   // [64, 65]
    const float* Wv = (const float*)d_in[3];   // [65, 65]
    float* out = (float*)d_out;                // [32, 2048, 65]

    float* gA = nullptr; float* gG = nullptr; float* gT = nullptr; float* gM = nullptr;
    cudaGetSymbolAddress((void**)&gA, g_A);
    cudaGetSymbolAddress((void**)&gG, g_G);
    cudaGetSymbolAddress((void**)&gT, g_T);
    cudaGetSymbolAddress((void**)&gM, g_M);

    k_A<<<(DSQ + 255) / 256, 256>>>(Wq, Wk);
    k_gram<<<dim3(NGC, BB), 256>>>(x);
    k_reduce<<<dim3(17, BB), 256>>>();
    k_mm65<<<dim3(5, BB), 256>>>(gA, 0, gG, DSQ, gT);   // T = A * G (G symmetric)
    k_mm65<<<dim3(5, BB), 256>>>(gT, DSQ, Wv, 0, gM);   // M = T * Wv^T
    k_out<<<dim3(NOC, BB), 256>>>(x, out);
}

// round 5
// speedup vs baseline: 1.1433x; 1.0036x over previous
#include <cuda_runtime.h>

// Problem constants
#define BB   32
#define NN   2048
#define DD   65
#define HH   64
#define DSQ  (DD*DD)        // 4225
#define GSUB 64             // gram sub-chunk rows (smem tile)
#define NSUB 4              // sub-chunks accumulated per block
#define GCH  (GSUB*NSUB)    // 256 rows per gram block
#define NGC  (NN/GCH)       // 8 partials per batch
#define OCH  64             // out chunk rows
#define NOC  (NN/OCH)       // 32

typedef unsigned long long ull;

// Scratch (no allocations allowed)
__device__ float g_Gpart[BB * NGC * DSQ];   // partial Gram matrices (~4.3 MB)
__device__ float g_M[BB * DSQ];             // M = A * G * Wv^T per batch

// ---- packed fp32x2 helpers (Blackwell FFMA2 path) ----
__device__ __forceinline__ ull pack2(float x) {
    ull d; unsigned u = __float_as_uint(x);
    asm("mov.b64 %0, {%1, %1};" : "=l"(d) : "r"(u));
    return d;
}
__device__ __forceinline__ ull fma2(ull a, ull b, ull c) {
    ull d;
    asm("fma.rn.f32x2 %0, %1, %2, %3;" : "=l"(d) : "l"(a), "l"(b), "l"(c));
    return d;
}
__device__ __forceinline__ void unpack2(ull d, float& lo, float& hi) {
    unsigned a, b;
    asm("mov.b64 {%0, %1}, %2;" : "=r"(a), "=r"(b) : "l"(d));
    lo = __uint_as_float(a); hi = __uint_as_float(b);
}

// ---------------------------------------------------------------------------
// Kernel 1: partial Gram for a 256-row chunk (4 x 64-row smem tiles,
// register accumulation across tiles). FFMA2 inner loop.
// ---------------------------------------------------------------------------
__global__ void __launch_bounds__(256) k_gram(const float* __restrict__ x) {
    __shared__ __align__(16) float xs[GSUB * 80];

    const int b = blockIdx.y, c = blockIdx.x;
    const int tid = threadIdx.x;
    const int ty = tid >> 4, tx = tid & 15;
    const int p0 = tx, p1 = 16 + tx, p2 = (tx == 0) ? 32 : 33;  // pair 33 = pad

    for (int idx = tid; idx < GSUB * 15; idx += 256) {
        int r = idx / 15, col = 65 + idx % 15;
        xs[r * 80 + col] = 0.f;
    }

    ull acc[5][3];
#pragma unroll
    for (int u = 0; u < 5; ++u)
#pragma unroll
        for (int v = 0; v < 3; ++v) acc[u][v] = 0ull;

    for (int s = 0; s < NSUB; ++s) {
        const float* xp = x + ((size_t)b * NN + (size_t)c * GCH + (size_t)s * GSUB) * DD;
        __syncthreads();
        for (int idx = tid; idx < GSUB * DD; idx += 256) {
            int r = idx / DD, col = idx - r * DD;
            xs[r * 80 + col] = xp[idx];
        }
        __syncthreads();

#pragma unroll 4
        for (int k = 0; k < GSUB; ++k) {
            const float* xr = xs + k * 80;
            const ull* xd = (const ull*)xr;
            ull b0 = xd[p0], b1 = xd[p1], b2 = xd[p2];
#pragma unroll
            for (int u = 0; u < 5; ++u) {
                ull ad = pack2(xr[ty + 16 * u]);
                acc[u][0] = fma2(ad, b0, acc[u][0]);
                acc[u][1] = fma2(ad, b1, acc[u][1]);
                acc[u][2] = fma2(ad, b2, acc[u][2]);
            }
        }
    }

    float* gp = g_Gpart + (size_t)(b * NGC + c) * DSQ;
    const int pv[3] = {p0, p1, p2};
#pragma unroll
    for (int u = 0; u < 5; ++u) {
        int i = ty + 16 * u;
        if (i >= DD) continue;
#pragma unroll
        for (int v = 0; v < 3; ++v) {
            int j0 = 2 * pv[v];
            float lo, hi;
            unpack2(acc[u][v], lo, hi);
            if (j0     < DD) gp[i * DD + j0]     = lo;
            if (j0 + 1 < DD) gp[i * DD + j0 + 1] = hi;
        }
    }
}

// ---------------------------------------------------------------------------
// Kernel 2 (fused mid): per batch b —
//   G = sum of 8 partial Grams; A = Wq^T Wk; T = A*G; M = T*Wv^T  -> g_M
// grid 32, block 256 (16x16). All phases use the FFMA2 5x3 micro-kernel.
// Dynamic smem layout (floats, pitch 68):
//   SG[80*68] | SA[80*68] | ST[80*68] | SW[65*68]
// Pad rows/cols hold garbage; all garbage lanes die at guarded stores.
// ---------------------------------------------------------------------------
#define PITCH 68
#define ROWS80 (80 * PITCH)     // 5440
__global__ void __launch_bounds__(256) k_mid2(const float* __restrict__ Wq,
                                              const float* __restrict__ Wk,
                                              const float* __restrict__ Wv) {
    extern __shared__ __align__(16) float sm[];
    float* SG = sm;                      // Gram [k][j]
    float* SA = sm + ROWS80;             // A    [i][k]
    float* ST = sm + 2 * ROWS80;         // Wq [h][i], then T [i][k]
    float* SW = sm + 3 * ROWS80;         // Wk [h][j], then Wv^T [k][j]

    const int b = blockIdx.x;
    const int tid = threadIdx.x;
    const int ty = tid >> 4, tx = tid & 15;
    const int p0 = tx, p1 = 16 + tx, p2 = (tx == 0) ? 32 : 33;
    const int pv[3] = {p0, p1, p2};

    // ---- stage: reduce partial Grams, load Wq, Wk ----
    {
        const float* gp = g_Gpart + (size_t)b * NGC * DSQ;
        for (int idx = tid; idx < DSQ; idx += 256) {
            int k = idx / DD, j = idx - k * DD;
            float s0 = 0.f, s1 = 0.f, s2 = 0.f, s3 = 0.f;
#pragma unroll
            for (int c = 0; c < NGC; c += 4) {
                s0 += gp[(c + 0) * DSQ + idx];
                s1 += gp[(c + 1) * DSQ + idx];
                s2 += gp[(c + 2) * DSQ + idx];
                s3 += gp[(c + 3) * DSQ + idx];
            }
            SG[k * PITCH + j] = (s0 + s1) + (s2 + s3);
        }
        for (int idx = tid; idx < HH * DD; idx += 256) {
            int h = idx / DD, i = idx - h * DD;
            ST[h * PITCH + i] = Wq[idx];
            SW[h * PITCH + i] = Wk[idx];
        }
    }
    __syncthreads();

    // ---- phase 0: A[i][j] = sum_h Wq[h][i] * Wk[h][j] ----
    {
        ull acc[5][3];
#pragma unroll
        for (int u = 0; u < 5; ++u)
#pragma unroll
            for (int v = 0; v < 3; ++v) acc[u][v] = 0ull;
#pragma unroll 4
        for (int h = 0; h < HH; ++h) {
            const float* qr = ST + h * PITCH;
            const ull* kr = (const ull*)(SW + h * PITCH);
            ull b0 = kr[p0], b1 = kr[p1], b2 = kr[p2];
#pragma unroll
            for (int u = 0; u < 5; ++u) {
                ull ad = pack2(qr[ty + 16 * u]);
                acc[u][0] = fma2(ad, b0, acc[u][0]);
                acc[u][1] = fma2(ad, b1, acc[u][1]);
                acc[u][2] = fma2(ad, b2, acc[u][2]);
            }
        }
        __syncthreads();   // everyone done reading ST/SW before SA writes? SA is distinct; sync before reads of SA below anyway
#pragma unroll
        for (int u = 0; u < 5; ++u) {
            int i = ty + 16 * u;
            ull* ap = (ull*)(SA + i * PITCH);
#pragma unroll
            for (int v = 0; v < 3; ++v) ap[pv[v]] = acc[u][v];
        }
    }
    __syncthreads();

    // ---- phase 1: T[i][j] = sum_k A[i][k] * G[k][j] ----
    ull accT[5][3];
    {
#pragma unroll
        for (int u = 0; u < 5; ++u)
#pragma unroll
            for (int v = 0; v < 3; ++v) accT[u][v] = 0ull;
#pragma unroll 5
        for (int k = 0; k < DD; ++k) {
            const ull* gr = (const ull*)(SG + k * PITCH);
            ull b0 = gr[p0], b1 = gr[p1], b2 = gr[p2];
#pragma unroll
            for (int u = 0; u < 5; ++u) {
                ull ad = pack2(SA[(ty + 16 * u) * PITCH + k]);
                accT[u][0] = fma2(ad, b0, accT[u][0]);
                accT[u][1] = fma2(ad, b1, accT[u][1]);
                accT[u][2] = fma2(ad, b2, accT[u][2]);
            }
        }
    }
    __syncthreads();   // all SA/SG reads done; ST (Wq) and SW (Wk) free

    // store T into ST; load Wv^T into SW (SW[k][j] = Wv[j][k], coalesced reads)
#pragma unroll
    for (int u = 0; u < 5; ++u) {
        int i = ty + 16 * u;
        ull* tp = (ull*)(ST + i * PITCH);
#pragma unroll
        for (int v = 0; v < 3; ++v) tp[pv[v]] = accT[u][v];
    }
    for (int idx = tid; idx < DSQ; idx += 256) {
        int j = idx / DD, k = idx - j * DD;
        SW[k * PITCH + j] = Wv[idx];
    }
    __syncthreads();

    // ---- phase 2: M[i][j] = sum_k T[i][k] * WvT[k][j] ----
    {
        ull acc[5][3];
#pragma unroll
        for (int u = 0; u < 5; ++u)
#pragma unroll
            for (int v = 0; v < 3; ++v) acc[u][v] = 0ull;
#pragma unroll 5
        for (int k = 0; k < DD; ++k) {
            const ull* wr = (const ull*)(SW + k * PITCH);
            ull b0 = wr[p0], b1 = wr[p1], b2 = wr[p2];
#pragma unroll
            for (int u = 0; u < 5; ++u) {
                ull ad = pack2(ST[(ty + 16 * u) * PITCH + k]);
                acc[u][0] = fma2(ad, b0, acc[u][0]);
                acc[u][1] = fma2(ad, b1, acc[u][1]);
                acc[u][2] = fma2(ad, b2, acc[u][2]);
            }
        }
        float* Mb = g_M + (size_t)b * DSQ;
#pragma unroll
        for (int u = 0; u < 5; ++u) {
            int i = ty + 16 * u;
            if (i >= DD) continue;
#pragma unroll
            for (int v = 0; v < 3; ++v) {
                int j0 = 2 * pv[v];
                float lo, hi;
                unpack2(acc[u][v], lo, hi);
                if (j0     < DD) Mb[i * DD + j0]     = lo;
                if (j0 + 1 < DD) Mb[i * DD + j0 + 1] = hi;
            }
        }
    }
}

// ---------------------------------------------------------------------------
// Kernel 3: out_chunk = x_chunk * M_b.  FFMA2 inner loop.
// ---------------------------------------------------------------------------
__global__ void __launch_bounds__(256) k_out(const float* __restrict__ x,
                                             float* __restrict__ out) {
    __shared__ __align__(16) float Ms[DD * 68];
    __shared__ __align__(16) float xs[OCH * 66];

    const int b = blockIdx.y, c = blockIdx.x;
    const float* xp = x + ((size_t)b * NN + (size_t)c * OCH) * DD;
    float* op = out + ((size_t)b * NN + (size_t)c * OCH) * DD;
    const int tid = threadIdx.x;

    const float* Mg = g_M + (size_t)b * DSQ;
    for (int idx = tid; idx < DSQ; idx += 256) {
        int k = idx / DD, j = idx - k * DD;
        Ms[k * 68 + j] = Mg[idx];
    }
    for (int idx = tid; idx < DD * 3; idx += 256) {
        int k = idx / 3, t = idx % 3;
        Ms[k * 68 + 65 + t] = 0.f;
    }
    for (int idx = tid; idx < OCH * DD; idx += 256) {
        int r = idx / DD, k = idx - r * DD;
        xs[r * 66 + k] = xp[idx];
    }
    __syncthreads();

    const int ty = tid >> 4, tx = tid & 15;
    const int p0 = tx, p1 = 16 + tx, p2 = (tx == 0) ? 32 : 33;

    ull acc[4][3];
#pragma unroll
    for (int u = 0; u < 4; ++u)
#pragma unroll
        for (int v = 0; v < 3; ++v) acc[u][v] = 0ull;

#pragma unroll 5
    for (int k = 0; k < DD; ++k) {
        const ull* mr = (const ull*)(Ms + k * 68);
        ull m0 = mr[p0], m1 = mr[p1], m2 = mr[p2];
#pragma unroll
        for (int u = 0; u < 4; ++u) {
            ull ad = pack2(xs[(ty + 16 * u) * 66 + k]);
            acc[u][0] = fma2(ad, m0, acc[u][0]);
            acc[u][1] = fma2(ad, m1, acc[u][1]);
            acc[u][2] = fma2(ad, m2, acc[u][2]);
        }
    }

    const int pv[3] = {p0, p1, p2};
#pragma unroll
    for (int u = 0; u < 4; ++u) {
        int r = ty + 16 * u;
#pragma unroll
        for (int v = 0; v < 3; ++v) {
            int j0 = 2 * pv[v];
            float lo, hi;
            unpack2(acc[u][v], lo, hi);
            if (j0     < DD) op[r * DD + j0]     = lo;
            if (j0 + 1 < DD) op[r * DD + j0 + 1] = hi;
        }
    }
}

// ---------------------------------------------------------------------------
extern "C" void kernel_launch(void* const* d_in, const int* in_sizes, int n_in,
                              void* d_out, int out_size) {
    const float* x  = (const float*)d_in[0];   // [32, 2048, 65]
    const float* Wq = (const float*)d_in[1];   // [64, 65]
    const float* Wk = (const float*)d_in[2];   // [64, 65]
    const float* Wv = (const float*)d_in[3];   // [65, 65]
    float* out = (float*)d_out;                // [32, 2048, 65]

    const int smem_mid = (3 * ROWS80 + DD * PITCH) * 4;   // (16320+4420)*4 = 82960 B
    static int attr_done = 0;
    if (!attr_done) {
        cudaFuncSetAttribute(k_mid2, cudaFuncAttributeMaxDynamicSharedMemorySize, smem_mid);
        attr_done = 1;
    }

    k_gram<<<dim3(NGC, BB), 256>>>(x);
    k_mid2<<<BB, 256, smem_mid>>>(Wq, Wk, Wv);
    k_out<<<dim3(NOC, BB), 256>>>(x, out);
}

// round 6
// speedup vs baseline: 1.1605x; 1.0151x over previous
#include <cuda_runtime.h>

// Problem constants
#define BB   32
#define NN   2048
#define DD   65
#define HH   64
#define DSQ  (DD*DD)        // 4225
#define GCH  64             // gram chunk rows per block
#define NGC  (NN/GCH)       // 32 partials per batch
#define OCH  64             // out chunk rows
#define NOC  (NN/OCH)       // 32

typedef unsigned long long ull;

// Scratch (no allocations allowed)
__device__ float g_Gpart[BB * NGC * DSQ];   // partial Gram matrices (~17.3 MB)
__device__ float g_G[BB * DSQ];             // reduced Gram
__device__ float g_M[BB * DSQ];             // M = A * G * Wv^T per batch

// ---- packed fp32x2 helpers (Blackwell FFMA2 path) ----
__device__ __forceinline__ ull pack2(float x) {
    ull d; unsigned u = __float_as_uint(x);
    asm("mov.b64 %0, {%1, %1};" : "=l"(d) : "r"(u));
    return d;
}
__device__ __forceinline__ ull fma2(ull a, ull b, ull c) {
    ull d;
    asm("fma.rn.f32x2 %0, %1, %2, %3;" : "=l"(d) : "l"(a), "l"(b), "l"(c));
    return d;
}
__device__ __forceinline__ void unpack2(ull d, float& lo, float& hi) {
    unsigned a, b;
    asm("mov.b64 {%0, %1}, %2;" : "=r"(a), "=r"(b) : "l"(d));
    lo = __uint_as_float(a); hi = __uint_as_float(b);
}

// ---------------------------------------------------------------------------
// Kernel 1: partial Gram for a 64-row chunk. FFMA2, dup-buffer a-operand.
// xs[64][68]: b-side pairs (cols j). xdup[64][160]: a-side duplicated pairs.
// No zero-fill: every global store is element-guarded.
// grid (32, 32), block 256, dynamic smem 58368 B.
// ---------------------------------------------------------------------------
__global__ void __launch_bounds__(256) k_gram(const float* __restrict__ x) {
    extern __shared__ __align__(16) float smg[];
    float* xs   = smg;               // 64*68
    float* xdup = smg + GCH * 68;    // 64*160

    const int b = blockIdx.y, c = blockIdx.x;
    const int tid = threadIdx.x;
    const float* xp = x + ((size_t)b * NN + (size_t)c * GCH) * DD;

    for (int idx = tid; idx < GCH * DD; idx += 256) {
        int r = idx / DD, col = idx - r * DD;
        float v = xp[idx];
        xs[r * 68 + col] = v;
        xdup[r * 160 + 2 * col]     = v;
        xdup[r * 160 + 2 * col + 1] = v;
    }
    __syncthreads();

    const int ty = tid >> 4, tx = tid & 15;
    const int p0 = tx, p1 = 16 + tx, p2 = (tx == 0) ? 32 : 33;  // pair 33 = pad

    ull acc[5][3];
#pragma unroll
    for (int u = 0; u < 5; ++u)
#pragma unroll
        for (int v = 0; v < 3; ++v) acc[u][v] = 0ull;

#pragma unroll 4
    for (int k = 0; k < GCH; ++k) {
        const ull* xd = (const ull*)(xs + k * 68);      // b-side pairs
        const ull* ar = (const ull*)(xdup + k * 160);   // a-side dup pairs
        ull b0 = xd[p0], b1 = xd[p1], b2 = xd[p2];
#pragma unroll
        for (int u = 0; u < 5; ++u) {
            ull ad = ar[ty + 16 * u];
            acc[u][0] = fma2(ad, b0, acc[u][0]);
            acc[u][1] = fma2(ad, b1, acc[u][1]);
            acc[u][2] = fma2(ad, b2, acc[u][2]);
        }
    }

    float* gp = g_Gpart + (size_t)(b * NGC + c) * DSQ;
    const int pv[3] = {p0, p1, p2};
#pragma unroll
    for (int u = 0; u < 5; ++u) {
        int i = ty + 16 * u;
        if (i >= DD) continue;
#pragma unroll
        for (int v = 0; v < 3; ++v) {
            int j0 = 2 * pv[v];
            float lo, hi;
            unpack2(acc[u][v], lo, hi);
            if (j0     < DD) gp[i * DD + j0]     = lo;
            if (j0 + 1 < DD) gp[i * DD + j0 + 1] = hi;
        }
    }
}

// ---------------------------------------------------------------------------
// Kernel 2: reduce 32 partial Grams -> g_G.  grid (17, 32), block 256.
// ---------------------------------------------------------------------------
__global__ void k_reduce() {
    const int b = blockIdx.y;
    int idx = blockIdx.x * 256 + threadIdx.x;
    if (idx >= DSQ) return;
    const float* gp = g_Gpart + (size_t)b * NGC * DSQ + idx;
    float s0 = 0.f, s1 = 0.f, s2 = 0.f, s3 = 0.f;
#pragma unroll
    for (int c = 0; c < NGC; c += 4) {
        s0 += gp[(c + 0) * DSQ];
        s1 += gp[(c + 1) * DSQ];
        s2 += gp[(c + 2) * DSQ];
        s3 += gp[(c + 3) * DSQ];
    }
    g_G[b * DSQ + idx] = (s0 + s1) + (s2 + s3);
}

// ---------------------------------------------------------------------------
// Kernel 3 (fused mid): per batch b — A = Wq^T Wk; T = A*G; M = T*Wv^T -> g_M
// grid 32, block 256 (16x16). FFMA2 5x3 micro-kernel, pack2 variant.
// Dynamic smem (floats, pitch 68): SG[80*68] | SA[80*68] | ST[80*68] | SW[65*68]
// ---------------------------------------------------------------------------
#define PITCH 68
#define ROWS80 (80 * PITCH)     // 5440
__global__ void __launch_bounds__(256) k_mid2(const float* __restrict__ Wq,
                                              const float* __restrict__ Wk,
                                              const float* __restrict__ Wv) {
    extern __shared__ __align__(16) float sm[];
    float* SG = sm;                      // Gram [k][j]
    float* SA = sm + ROWS80;             // A    [i][k]
    float* ST = sm + 2 * ROWS80;         // Wq [h][i], then T [i][k]
    float* SW = sm + 3 * ROWS80;         // Wk [h][j], then Wv^T [k][j]

    const int b = blockIdx.x;
    const int tid = threadIdx.x;
    const int ty = tid >> 4, tx = tid & 15;
    const int p0 = tx, p1 = 16 + tx, p2 = (tx == 0) ? 32 : 33;
    const int pv[3] = {p0, p1, p2};

    // ---- stage: G, Wq, Wk ----
    for (int idx = tid; idx < DSQ; idx += 256) {
        int k = idx / DD, j = idx - k * DD;
        SG[k * PITCH + j] = g_G[(size_t)b * DSQ + idx];
    }
    for (int idx = tid; idx < HH * DD; idx += 256) {
        int h = idx / DD, i = idx - h * DD;
        ST[h * PITCH + i] = Wq[idx];
        SW[h * PITCH + i] = Wk[idx];
    }
    __syncthreads();

    // ---- phase 0: A[i][j] = sum_h Wq[h][i] * Wk[h][j] ----
    {
        ull acc[5][3];
#pragma unroll
        for (int u = 0; u < 5; ++u)
#pragma unroll
            for (int v = 0; v < 3; ++v) acc[u][v] = 0ull;
#pragma unroll 4
        for (int h = 0; h < HH; ++h) {
            const float* qr = ST + h * PITCH;
            const ull* kr = (const ull*)(SW + h * PITCH);
            ull b0 = kr[p0], b1 = kr[p1], b2 = kr[p2];
#pragma unroll
            for (int u = 0; u < 5; ++u) {
                ull ad = pack2(qr[ty + 16 * u]);
                acc[u][0] = fma2(ad, b0, acc[u][0]);
                acc[u][1] = fma2(ad, b1, acc[u][1]);
                acc[u][2] = fma2(ad, b2, acc[u][2]);
            }
        }
        __syncthreads();
#pragma unroll
        for (int u = 0; u < 5; ++u) {
            int i = ty + 16 * u;
            ull* ap = (ull*)(SA + i * PITCH);
#pragma unroll
            for (int v = 0; v < 3; ++v) ap[pv[v]] = acc[u][v];
        }
    }
    __syncthreads();

    // ---- phase 1: T[i][j] = sum_k A[i][k] * G[k][j] ----
    ull accT[5][3];
#pragma unroll
    for (int u = 0; u < 5; ++u)
#pragma unroll
        for (int v = 0; v < 3; ++v) accT[u][v] = 0ull;
#pragma unroll 5
    for (int k = 0; k < DD; ++k) {
        const ull* gr = (const ull*)(SG + k * PITCH);
        ull b0 = gr[p0], b1 = gr[p1], b2 = gr[p2];
#pragma unroll
        for (int u = 0; u < 5; ++u) {
            ull ad = pack2(SA[(ty + 16 * u) * PITCH + k]);
            accT[u][0] = fma2(ad, b0, accT[u][0]);
            accT[u][1] = fma2(ad, b1, accT[u][1]);
            accT[u][2] = fma2(ad, b2, accT[u][2]);
        }
    }
    __syncthreads();

    // store T into ST; load Wv^T into SW
#pragma unroll
    for (int u = 0; u < 5; ++u) {
        int i = ty + 16 * u;
        ull* tp = (ull*)(ST + i * PITCH);
#pragma unroll
        for (int v = 0; v < 3; ++v) tp[pv[v]] = accT[u][v];
    }
    for (int idx = tid; idx < DSQ; idx += 256) {
        int j = idx / DD, k = idx - j * DD;
        SW[k * PITCH + j] = Wv[idx];
    }
    __syncthreads();

    // ---- phase 2: M[i][j] = sum_k T[i][k] * WvT[k][j] ----
    {
        ull acc[5][3];
#pragma unroll
        for (int u = 0; u < 5; ++u)
#pragma unroll
            for (int v = 0; v < 3; ++v) acc[u][v] = 0ull;
#pragma unroll 5
        for (int k = 0; k < DD; ++k) {
            const ull* wr = (const ull*)(SW + k * PITCH);
            ull b0 = wr[p0], b1 = wr[p1], b2 = wr[p2];
#pragma unroll
            for (int u = 0; u < 5; ++u) {
                ull ad = pack2(ST[(ty + 16 * u) * PITCH + k]);
                acc[u][0] = fma2(ad, b0, acc[u][0]);
                acc[u][1] = fma2(ad, b1, acc[u][1]);
                acc[u][2] = fma2(ad, b2, acc[u][2]);
            }
        }
        float* Mb = g_M + (size_t)b * DSQ;
#pragma unroll
        for (int u = 0; u < 5; ++u) {
            int i = ty + 16 * u;
            if (i >= DD) continue;
#pragma unroll
            for (int v = 0; v < 3; ++v) {
                int j0 = 2 * pv[v];
                float lo, hi;
                unpack2(acc[u][v], lo, hi);
                if (j0     < DD) Mb[i * DD + j0]     = lo;
                if (j0 + 1 < DD) Mb[i * DD + j0 + 1] = hi;
            }
        }
    }
}

// ---------------------------------------------------------------------------
// Kernel 4: out_chunk = x_chunk * M_b. FFMA2, dup-buffer a-operand.
// Ms[65][68]: b-side pairs. xdup[64][132]: x duplicated along k.
// grid (32, 32), block 256, dynamic smem 51472 B.
// ---------------------------------------------------------------------------
__global__ void __launch_bounds__(256) k_out(const float* __restrict__ x,
                                             float* __restrict__ out) {
    extern __shared__ __align__(16) float smo[];
    float* Ms   = smo;               // 65*68
    float* xdup = smo + DD * 68;     // 64*132

    const int b = blockIdx.y, c = blockIdx.x;
    const float* xp = x + ((size_t)b * NN + (size_t)c * OCH) * DD;
    float* op = out + ((size_t)b * NN + (size_t)c * OCH) * DD;
    const int tid = threadIdx.x;

    const float* Mg = g_M + (size_t)b * DSQ;
    for (int idx = tid; idx < DSQ; idx += 256) {
        int k = idx / DD, j = idx - k * DD;
        Ms[k * 68 + j] = Mg[idx];
    }
    for (int idx = tid; idx < OCH * DD; idx += 256) {
        int r = idx / DD, k = idx - r * DD;
        float v = xp[idx];
        xdup[r * 132 + 2 * k]     = v;
        xdup[r * 132 + 2 * k + 1] = v;
    }
    __syncthreads();

    const int ty = tid >> 4, tx = tid & 15;
    const int p0 = tx, p1 = 16 + tx, p2 = (tx == 0) ? 32 : 33;

    ull acc[4][3];
#pragma unroll
    for (int u = 0; u < 4; ++u)
#pragma unroll
        for (int v = 0; v < 3; ++v) acc[u][v] = 0ull;

    const ull* xdu = (const ull*)xdup;   // pitch 66 ulls per row
#pragma unroll 5
    for (int k = 0; k < DD; ++k) {
        const ull* mr = (const ull*)(Ms + k * 68);
        ull m0 = mr[p0], m1 = mr[p1], m2 = mr[p2];
#pragma unroll
        for (int u = 0; u < 4; ++u) {
            ull ad = xdu[(ty + 16 * u) * 66 + k];
            acc[u][0] = fma2(ad, m0, acc[u][0]);
            acc[u][1] = fma2(ad, m1, acc[u][1]);
            acc[u][2] = fma2(ad, m2, acc[u][2]);
        }
    }

    const int pv[3] = {p0, p1, p2};
#pragma unroll
    for (int u = 0; u < 4; ++u) {
        int r = ty + 16 * u;
#pragma unroll
        for (int v = 0; v < 3; ++v) {
            int j0 = 2 * pv[v];
            float lo, hi;
            unpack2(acc[u][v], lo, hi);
            if (j0     < DD) op[r * DD + j0]     = lo;
            if (j0 + 1 < DD) op[r * DD + j0 + 1] = hi;
        }
    }
}

// ---------------------------------------------------------------------------
extern "C" void kernel_launch(void* const* d_in, const int* in_sizes, int n_in,
                              void* d_out, int out_size) {
    const float* x  = (const float*)d_in[0];   // [32, 2048, 65]
    const float* Wq = (const float*)d_in[1];   // [64, 65]
    const float* Wk = (const float*)d_in[2];   // [64, 65]
    const float* Wv = (const float*)d_in[3];   // [65, 65]
    float* out = (float*)d_out;                // [32, 2048, 65]

    const int smem_gram = (GCH * 68 + GCH * 160) * 4;      // 58368 B
    const int smem_mid  = (3 * ROWS80 + DD * PITCH) * 4;   // 82960 B
    const int smem_out  = (DD * 68 + OCH * 132) * 4;       // 51472 B
    cudaFuncSetAttribute(k_gram, cudaFuncAttributeMaxDynamicSharedMemorySize, smem_gram);
    cudaFuncSetAttribute(k_mid2, cudaFuncAttributeMaxDynamicSharedMemorySize, smem_mid);
    cudaFuncSetAttribute(k_out,  cudaFuncAttributeMaxDynamicSharedMemorySize, smem_out);

    k_gram<<<dim3(NGC, BB), 256, smem_gram>>>(x);
    k_reduce<<<dim3(17, BB), 256>>>();
    k_mid2<<<BB, 256, smem_mid>>>(Wq, Wk, Wv);
    k_out<<<dim3(NOC, BB), 256, smem_out>>>(x, out);
}

// round 7
// speedup vs baseline: 1.2269x; 1.0572x over previous
#include <cuda_runtime.h>

// Problem constants
#define BB   32
#define NN   2048
#define DD   65
#define HH   64
#define DSQ  (DD*DD)        // 4225
#define GSUB 64             // gram sub-tile rows
#define GNS  2              // sub-tiles per gram block
#define GCH  (GSUB*GNS)     // 128 rows per gram block
#define NGC  (NN/GCH)       // 16 partials per batch
#define OCH  128            // out chunk rows
#define NOC  (NN/OCH)       // 16

typedef unsigned long long ull;

// Scratch (no allocations allowed)
__device__ float g_Gpart[BB * NGC * DSQ];   // partial Gram matrices (~8.6 MB)
__device__ float g_G[BB * DSQ];             // reduced Gram
__device__ float g_M[BB * DSQ];             // M = A * G * Wv^T per batch

// ---- packed fp32x2 helpers ----
__device__ __forceinline__ ull pack2(float x) {
    ull d; unsigned u = __float_as_uint(x);
    asm("mov.b64 %0, {%1, %1};" : "=l"(d) : "r"(u));
    return d;
}
__device__ __forceinline__ ull fma2(ull a, ull b, ull c) {
    ull d;
    asm("fma.rn.f32x2 %0, %1, %2, %3;" : "=l"(d) : "l"(a), "l"(b), "l"(c));
    return d;
}
__device__ __forceinline__ void unpack2(ull d, float& lo, float& hi) {
    unsigned a, b;
    asm("mov.b64 {%0, %1}, %2;" : "=r"(a), "=r"(b) : "l"(d));
    lo = __uint_as_float(a); hi = __uint_as_float(b);
}

// ---------------------------------------------------------------------------
// Kernel 1: partial Gram, 128 rows per block as 2 x 64-row smem tiles with
// register accumulation. FFMA2: a-side dup buffer, b-side natural pairs.
// grid (16, 32), block 256, dynamic smem 58368 B.
// ---------------------------------------------------------------------------
__global__ void __launch_bounds__(256) k_gram(const float* __restrict__ x) {
    extern __shared__ __align__(16) float smg[];
    float* xs   = smg;                // 64*68  (b-side pairs)
    float* xdup = smg + GSUB * 68;    // 64*160 (a-side duplicated)

    const int b = blockIdx.y, c = blockIdx.x;
    const int tid = threadIdx.x;
    const int ty = tid >> 4, tx = tid & 15;
    const int p0 = tx, p1 = 16 + tx, p2 = (tx == 0) ? 32 : 33;  // pair 33 = garbage pad (guarded)

    ull acc[5][3];
#pragma unroll
    for (int u = 0; u < 5; ++u)
#pragma unroll
        for (int v = 0; v < 3; ++v) acc[u][v] = 0ull;

    for (int s = 0; s < GNS; ++s) {
        const float* xp = x + ((size_t)b * NN + (size_t)c * GCH + (size_t)s * GSUB) * DD;
        __syncthreads();
        for (int idx = tid; idx < GSUB * DD; idx += 256) {
            int r = idx / DD, col = idx - r * DD;
            float v = xp[idx];
            xs[r * 68 + col] = v;
            xdup[r * 160 + 2 * col]     = v;
            xdup[r * 160 + 2 * col + 1] = v;
        }
        __syncthreads();

#pragma unroll 4
        for (int k = 0; k < GSUB; ++k) {
            const ull* xd = (const ull*)(xs + k * 68);
            const ull* ar = (const ull*)(xdup + k * 160);
            ull b0 = xd[p0], b1 = xd[p1], b2 = xd[p2];
#pragma unroll
            for (int u = 0; u < 5; ++u) {
                ull ad = ar[ty + 16 * u];
                acc[u][0] = fma2(ad, b0, acc[u][0]);
                acc[u][1] = fma2(ad, b1, acc[u][1]);
                acc[u][2] = fma2(ad, b2, acc[u][2]);
            }
        }
    }

    float* gp = g_Gpart + (size_t)(b * NGC + c) * DSQ;
    const int pv[3] = {p0, p1, p2};
#pragma unroll
    for (int u = 0; u < 5; ++u) {
        int i = ty + 16 * u;
        if (i >= DD) continue;
#pragma unroll
        for (int v = 0; v < 3; ++v) {
            int j0 = 2 * pv[v];
            float lo, hi;
            unpack2(acc[u][v], lo, hi);
            if (j0     < DD) gp[i * DD + j0]     = lo;
            if (j0 + 1 < DD) gp[i * DD + j0 + 1] = hi;
        }
    }
}

// ---------------------------------------------------------------------------
// Kernel 2: reduce 16 partial Grams -> g_G.  grid (17, 32), block 256.
// ---------------------------------------------------------------------------
__global__ void k_reduce() {
    const int b = blockIdx.y;
    int idx = blockIdx.x * 256 + threadIdx.x;
    if (idx >= DSQ) return;
    const float* gp = g_Gpart + (size_t)b * NGC * DSQ + idx;
    float s0 = 0.f, s1 = 0.f, s2 = 0.f, s3 = 0.f;
#pragma unroll
    for (int c = 0; c < NGC; c += 4) {
        s0 += gp[(c + 0) * DSQ];
        s1 += gp[(c + 1) * DSQ];
        s2 += gp[(c + 2) * DSQ];
        s3 += gp[(c + 3) * DSQ];
    }
    g_G[b * DSQ + idx] = (s0 + s1) + (s2 + s3);
}

// ---------------------------------------------------------------------------
// Kernel 3 (fused mid): per batch b — A = Wq^T Wk; T = A*G; M = T*Wv^T -> g_M
// grid 32, block 256. FFMA2 5x3 micro-kernel (pack2 variant, cold path).
// ---------------------------------------------------------------------------
#define PITCH 68
#define ROWS80 (80 * PITCH)
__global__ void __launch_bounds__(256) k_mid2(const float* __restrict__ Wq,
                                              const float* __restrict__ Wk,
                                              const float* __restrict__ Wv) {
    extern __shared__ __align__(16) float sm[];
    float* SG = sm;
    float* SA = sm + ROWS80;
    float* ST = sm + 2 * ROWS80;
    float* SW = sm + 3 * ROWS80;

    const int b = blockIdx.x;
    const int tid = threadIdx.x;
    const int ty = tid >> 4, tx = tid & 15;
    const int p0 = tx, p1 = 16 + tx, p2 = (tx == 0) ? 32 : 33;
    const int pv[3] = {p0, p1, p2};

    for (int idx = tid; idx < DSQ; idx += 256) {
        int k = idx / DD, j = idx - k * DD;
        SG[k * PITCH + j] = g_G[(size_t)b * DSQ + idx];
    }
    for (int idx = tid; idx < HH * DD; idx += 256) {
        int h = idx / DD, i = idx - h * DD;
        ST[h * PITCH + i] = Wq[idx];
        SW[h * PITCH + i] = Wk[idx];
    }
    __syncthreads();

    // phase 0: A = Wq^T Wk
    {
        ull acc[5][3];
#pragma unroll
        for (int u = 0; u < 5; ++u)
#pragma unroll
            for (int v = 0; v < 3; ++v) acc[u][v] = 0ull;
#pragma unroll 4
        for (int h = 0; h < HH; ++h) {
            const float* qr = ST + h * PITCH;
            const ull* kr = (const ull*)(SW + h * PITCH);
            ull b0 = kr[p0], b1 = kr[p1], b2 = kr[p2];
#pragma unroll
            for (int u = 0; u < 5; ++u) {
                ull ad = pack2(qr[ty + 16 * u]);
                acc[u][0] = fma2(ad, b0, acc[u][0]);
                acc[u][1] = fma2(ad, b1, acc[u][1]);
                acc[u][2] = fma2(ad, b2, acc[u][2]);
            }
        }
        __syncthreads();
#pragma unroll
        for (int u = 0; u < 5; ++u) {
            ull* ap = (ull*)(SA + (ty + 16 * u) * PITCH);
#pragma unroll
            for (int v = 0; v < 3; ++v) ap[pv[v]] = acc[u][v];
        }
    }
    __syncthreads();

    // phase 1: T = A*G
    ull accT[5][3];
#pragma unroll
    for (int u = 0; u < 5; ++u)
#pragma unroll
        for (int v = 0; v < 3; ++v) accT[u][v] = 0ull;
#pragma unroll 5
    for (int k = 0; k < DD; ++k) {
        const ull* gr = (const ull*)(SG + k * PITCH);
        ull b0 = gr[p0], b1 = gr[p1], b2 = gr[p2];
#pragma unroll
        for (int u = 0; u < 5; ++u) {
            ull ad = pack2(SA[(ty + 16 * u) * PITCH + k]);
            accT[u][0] = fma2(ad, b0, accT[u][0]);
            accT[u][1] = fma2(ad, b1, accT[u][1]);
            accT[u][2] = fma2(ad, b2, accT[u][2]);
        }
    }
    __syncthreads();

#pragma unroll
    for (int u = 0; u < 5; ++u) {
        ull* tp = (ull*)(ST + (ty + 16 * u) * PITCH);
#pragma unroll
        for (int v = 0; v < 3; ++v) tp[pv[v]] = accT[u][v];
    }
    for (int idx = tid; idx < DSQ; idx += 256) {
        int j = idx / DD, k = idx - j * DD;
        SW[k * PITCH + j] = Wv[idx];
    }
    __syncthreads();

    // phase 2: M = T*Wv^T
    {
        ull acc[5][3];
#pragma unroll
        for (int u = 0; u < 5; ++u)
#pragma unroll
            for (int v = 0; v < 3; ++v) acc[u][v] = 0ull;
#pragma unroll 5
        for (int k = 0; k < DD; ++k) {
            const ull* wr = (const ull*)(SW + k * PITCH);
            ull b0 = wr[p0], b1 = wr[p1], b2 = wr[p2];
#pragma unroll
            for (int u = 0; u < 5; ++u) {
                ull ad = pack2(ST[(ty + 16 * u) * PITCH + k]);
                acc[u][0] = fma2(ad, b0, acc[u][0]);
                acc[u][1] = fma2(ad, b1, acc[u][1]);
                acc[u][2] = fma2(ad, b2, acc[u][2]);
            }
        }
        float* Mb = g_M + (size_t)b * DSQ;
#pragma unroll
        for (int u = 0; u < 5; ++u) {
            int i = ty + 16 * u;
            if (i >= DD) continue;
#pragma unroll
            for (int v = 0; v < 3; ++v) {
                int j0 = 2 * pv[v];
                float lo, hi;
                unpack2(acc[u][v], lo, hi);
                if (j0     < DD) Mb[i * DD + j0]     = lo;
                if (j0 + 1 < DD) Mb[i * DD + j0 + 1] = hi;
            }
        }
    }
}

// ---------------------------------------------------------------------------
// Kernel 4: out_chunk = x_chunk * M_b, pair dimension = OUTPUT ROWS.
// acc lanes = (out[2p][j], out[2p+1][j]); a = natural x row-pair from
// transposed xsT[k][r] (pitch 130); b = M[k][j] duplicated (Msd, pitch 132).
// Tile: u<4 row-pairs (p = tx+16u -> 64 pairs = 128 rows), v<5 cols
// (j = ty+16v, clamped loads, guarded stores). Epilogue staged via smem
// (reuses xsT; bank pattern 2tx+ty -> conflict-free) then coalesced STG.
// grid (16, 32), block 256, dynamic smem 68640 B.
// ---------------------------------------------------------------------------
__global__ void __launch_bounds__(256) k_out(const float* __restrict__ x,
                                             float* __restrict__ out) {
    extern __shared__ __align__(16) float smo[];
    float* Msd = smo;                 // 65*132 dup'd M
    float* xsT = smo + DD * 132;      // 65*130 transposed x; reused as osm[128*65]
    float* osm = xsT;

    const int b = blockIdx.y, c = blockIdx.x;
    const float* xp = x + ((size_t)b * NN + (size_t)c * OCH) * DD;
    float* op = out + ((size_t)b * NN + (size_t)c * OCH) * DD;
    const int tid = threadIdx.x;

    const float* Mg = g_M + (size_t)b * DSQ;
    for (int idx = tid; idx < DSQ; idx += 256) {
        int k = idx / DD, j = idx - k * DD;
        float v = Mg[idx];
        Msd[k * 132 + 2 * j]     = v;
        Msd[k * 132 + 2 * j + 1] = v;
    }
    for (int idx = tid; idx < OCH * DD; idx += 256) {
        int r = idx / DD, k = idx - r * DD;
        xsT[k * 130 + r] = xp[idx];
    }
    __syncthreads();

    const int ty = tid >> 4, tx = tid & 15;
    int jv[5];
#pragma unroll
    for (int v = 0; v < 5; ++v) {
        int j = ty + 16 * v;
        jv[v] = (j < DD) ? j : (DD - 1);   // clamp loads; stores guarded by real j
    }

    ull acc[4][5];
#pragma unroll
    for (int u = 0; u < 4; ++u)
#pragma unroll
        for (int v = 0; v < 5; ++v) acc[u][v] = 0ull;

    const ull* xu = (const ull*)xsT;   // pitch 65 ulls per k
    const ull* mu = (const ull*)Msd;   // pitch 66 ulls per k
#pragma unroll 5
    for (int k = 0; k < DD; ++k) {
        ull a0 = xu[k * 65 + tx];
        ull a1 = xu[k * 65 + tx + 16];
        ull a2 = xu[k * 65 + tx + 32];
        ull a3 = xu[k * 65 + tx + 48];
        ull m0 = mu[k * 66 + jv[0]];
        ull m1 = mu[k * 66 + jv[1]];
        ull m2 = mu[k * 66 + jv[2]];
        ull m3 = mu[k * 66 + jv[3]];
        ull m4 = mu[k * 66 + jv[4]];
        acc[0][0] = fma2(a0, m0, acc[0][0]); acc[0][1] = fma2(a0, m1, acc[0][1]);
        acc[0][2] = fma2(a0, m2, acc[0][2]); acc[0][3] = fma2(a0, m3, acc[0][3]);
        acc[0][4] = fma2(a0, m4, acc[0][4]);
        acc[1][0] = fma2(a1, m0, acc[1][0]); acc[1][1] = fma2(a1, m1, acc[1][1]);
        acc[1][2] = fma2(a1, m2, acc[1][2]); acc[1][3] = fma2(a1, m3, acc[1][3]);
        acc[1][4] = fma2(a1, m4, acc[1][4]);
        acc[2][0] = fma2(a2, m0, acc[2][0]); acc[2][1] = fma2(a2, m1, acc[2][1]);
        acc[2][2] = fma2(a2, m2, acc[2][2]); acc[2][3] = fma2(a2, m3, acc[2][3]);
        acc[2][4] = fma2(a2, m4, acc[2][4]);
        acc[3][0] = fma2(a3, m0, acc[3][0]); acc[3][1] = fma2(a3, m1, acc[3][1]);
        acc[3][2] = fma2(a3, m2, acc[3][2]); acc[3][3] = fma2(a3, m3, acc[3][3]);
        acc[3][4] = fma2(a3, m4, acc[3][4]);
    }

    __syncthreads();   // all xsT reads done before osm overwrite

#pragma unroll
    for (int u = 0; u < 4; ++u) {
        int r0 = 2 * (tx + 16 * u);
#pragma unroll
        for (int v = 0; v < 5; ++v) {
            int j = ty + 16 * v;
            if (j < DD) {
                float lo, hi;
                unpack2(acc[u][v], lo, hi);
                osm[r0 * DD + j]       = lo;
                osm[(r0 + 1) * DD + j] = hi;
            }
        }
    }
    __syncthreads();

    for (int idx = tid; idx < OCH * DD; idx += 256)
        op[idx] = osm[idx];
}

// ---------------------------------------------------------------------------
extern "C" void kernel_launch(void* const* d_in, const int* in_sizes, int n_in,
                              void* d_out, int out_size) {
    const float* x  = (const float*)d_in[0];   // [32, 2048, 65]
    const float* Wq = (const float*)d_in[1];   // [64, 65]
    const float* Wk = (const float*)d_in[2];   // [64, 65]
    const float* Wv = (const float*)d_in[3];   // [65, 65]
    float* out = (float*)d_out;                // [32, 2048, 65]

    const int smem_gram = (GSUB * 68 + GSUB * 160) * 4;    // 58368 B
    const int smem_mid  = (3 * ROWS80 + DD * PITCH) * 4;   // 82960 B
    const int smem_out  = (DD * 132 + DD * 130) * 4;       // 68120 B
    cudaFuncSetAttribute(k_gram, cudaFuncAttributeMaxDynamicSharedMemorySize, smem_gram);
    cudaFuncSetAttribute(k_mid2, cudaFuncAttributeMaxDynamicSharedMemorySize, smem_mid);
    cudaFuncSetAttribute(k_out,  cudaFuncAttributeMaxDynamicSharedMemorySize, smem_out);

    k_gram<<<dim3(NGC, BB), 256, smem_gram>>>(x);
    k_reduce<<<dim3(17, BB), 256>>>();
    k_mid2<<<BB, 256, smem_mid>>>(Wq, Wk, Wv);
    k_out<<<dim3(NOC, BB), 256, smem_out>>>(x, out);
}

// round 8
// speedup vs baseline: 1.2876x; 1.0494x over previous
#include <cuda_runtime.h>

// Problem constants
#define BB   32
#define NN   2048
#define DD   65
#define HH   64
#define DSQ  (DD*DD)        // 4225
#define GSUB 64             // gram sub-tile rows
#define GNS  2              // sub-tiles per gram block
#define GCH  (GSUB*GNS)     // 128 rows per gram block
#define NGC  (NN/GCH)       // 16 partials per batch
#define OCH  128            // out chunk rows
#define NOC  (NN/OCH)       // 16

typedef unsigned long long ull;

// Scratch (no allocations allowed)
__device__ float g_Gpart[BB * NGC * DSQ];   // partial Gram matrices (~8.6 MB)
__device__ float g_G[BB * DSQ];             // reduced Gram
__device__ float g_M[BB * DSQ];             // M = A * G * Wv^T per batch

// ---- packed fp32x2 helpers ----
__device__ __forceinline__ ull pack2(float x) {
    ull d; unsigned u = __float_as_uint(x);
    asm("mov.b64 %0, {%1, %1};" : "=l"(d) : "r"(u));
    return d;
}
__device__ __forceinline__ ull fma2(ull a, ull b, ull c) {
    ull d;
    asm("fma.rn.f32x2 %0, %1, %2, %3;" : "=l"(d) : "l"(a), "l"(b), "l"(c));
    return d;
}
__device__ __forceinline__ void unpack2(ull d, float& lo, float& hi) {
    unsigned a, b;
    asm("mov.b64 {%0, %1}, %2;" : "=r"(a), "=r"(b) : "l"(d));
    lo = __uint_as_float(a); hi = __uint_as_float(b);
}

// ---------------------------------------------------------------------------
// Kernel 1: partial Gram, 128 rows per block as 2 x 64-row smem tiles with
// register accumulation. Single smem buffer: b-side natural ull pairs,
// a-side scalar broadcast + pack2. Static smem 17.5 KB -> occupancy reg-bound.
// grid (16, 32), block 256.
// ---------------------------------------------------------------------------
__global__ void __launch_bounds__(256, 4) k_gram(const float* __restrict__ x) {
    __shared__ __align__(16) float xs[GSUB * 68 + 16];   // +16 pad for clamped reads

    const int b = blockIdx.y, c = blockIdx.x;
    const int tid = threadIdx.x;
    const int ty = tid >> 4, tx = tid & 15;
    const int p0 = tx, p1 = 16 + tx, p2 = (tx == 0) ? 32 : 33;  // pair 33 = garbage pad (guarded)

    int iv[5];
#pragma unroll
    for (int u = 0; u < 5; ++u) {
        int i = ty + 16 * u;
        iv[u] = (i < DD) ? i : (DD - 1);    // clamp loads; stores use real i
    }

    ull acc[5][3];
#pragma unroll
    for (int u = 0; u < 5; ++u)
#pragma unroll
        for (int v = 0; v < 3; ++v) acc[u][v] = 0ull;

    for (int s = 0; s < GNS; ++s) {
        const float* xp = x + ((size_t)b * NN + (size_t)c * GCH + (size_t)s * GSUB) * DD;
        __syncthreads();
        for (int idx = tid; idx < GSUB * DD; idx += 256) {
            int r = idx / DD, col = idx - r * DD;
            xs[r * 68 + col] = xp[idx];
        }
        __syncthreads();

#pragma unroll 8
        for (int k = 0; k < GSUB; ++k) {
            const float* row = xs + k * 68;
            const ull* xd = (const ull*)row;
            ull b0 = xd[p0], b1 = xd[p1], b2 = xd[p2];
#pragma unroll
            for (int u = 0; u < 5; ++u) {
                ull ad = pack2(row[iv[u]]);
                acc[u][0] = fma2(ad, b0, acc[u][0]);
                acc[u][1] = fma2(ad, b1, acc[u][1]);
                acc[u][2] = fma2(ad, b2, acc[u][2]);
            }
        }
    }

    float* gp = g_Gpart + (size_t)(b * NGC + c) * DSQ;
    const int pv[3] = {p0, p1, p2};
#pragma unroll
    for (int u = 0; u < 5; ++u) {
        int i = ty + 16 * u;
        if (i >= DD) continue;
#pragma unroll
        for (int v = 0; v < 3; ++v) {
            int j0 = 2 * pv[v];
            float lo, hi;
            unpack2(acc[u][v], lo, hi);
            if (j0     < DD) gp[i * DD + j0]     = lo;
            if (j0 + 1 < DD) gp[i * DD + j0 + 1] = hi;
        }
    }
}

// ---------------------------------------------------------------------------
// Kernel 2: reduce 16 partial Grams -> g_G.  grid (17, 32), block 256.
// ---------------------------------------------------------------------------
__global__ void k_reduce() {
    const int b = blockIdx.y;
    int idx = blockIdx.x * 256 + threadIdx.x;
    if (idx >= DSQ) return;
    const float* gp = g_Gpart + (size_t)b * NGC * DSQ + idx;
    float s0 = 0.f, s1 = 0.f, s2 = 0.f, s3 = 0.f;
#pragma unroll
    for (int c = 0; c < NGC; c += 4) {
        s0 += gp[(c + 0) * DSQ];
        s1 += gp[(c + 1) * DSQ];
        s2 += gp[(c + 2) * DSQ];
        s3 += gp[(c + 3) * DSQ];
    }
    g_G[b * DSQ + idx] = (s0 + s1) + (s2 + s3);
}

// ---------------------------------------------------------------------------
// Kernel 3 (fused mid): per batch b — A = Wq^T Wk; T = A*G; M = T*Wv^T -> g_M
// grid 32, block 256. FFMA2 5x3 micro-kernel (pack2 variant).
// ---------------------------------------------------------------------------
#define PITCH 68
#define ROWS80 (80 * PITCH)
__global__ void __launch_bounds__(256) k_mid2(const float* __restrict__ Wq,
                                              const float* __restrict__ Wk,
                                              const float* __restrict__ Wv) {
    extern __shared__ __align__(16) float sm[];
    float* SG = sm;
    float* SA = sm + ROWS80;
    float* ST = sm + 2 * ROWS80;
    float* SW = sm + 3 * ROWS80;

    const int b = blockIdx.x;
    const int tid = threadIdx.x;
    const int ty = tid >> 4, tx = tid & 15;
    const int p0 = tx, p1 = 16 + tx, p2 = (tx == 0) ? 32 : 33;
    const int pv[3] = {p0, p1, p2};

    for (int idx = tid; idx < DSQ; idx += 256) {
        int k = idx / DD, j = idx - k * DD;
        SG[k * PITCH + j] = g_G[(size_t)b * DSQ + idx];
    }
    for (int idx = tid; idx < HH * DD; idx += 256) {
        int h = idx / DD, i = idx - h * DD;
        ST[h * PITCH + i] = Wq[idx];
        SW[h * PITCH + i] = Wk[idx];
    }
    __syncthreads();

    // phase 0: A = Wq^T Wk
    {
        ull acc[5][3];
#pragma unroll
        for (int u = 0; u < 5; ++u)
#pragma unroll
            for (int v = 0; v < 3; ++v) acc[u][v] = 0ull;
#pragma unroll 4
        for (int h = 0; h < HH; ++h) {
            const float* qr = ST + h * PITCH;
            const ull* kr = (const ull*)(SW + h * PITCH);
            ull b0 = kr[p0], b1 = kr[p1], b2 = kr[p2];
#pragma unroll
            for (int u = 0; u < 5; ++u) {
                ull ad = pack2(qr[ty + 16 * u]);
                acc[u][0] = fma2(ad, b0, acc[u][0]);
                acc[u][1] = fma2(ad, b1, acc[u][1]);
                acc[u][2] = fma2(ad, b2, acc[u][2]);
            }
        }
        __syncthreads();
#pragma unroll
        for (int u = 0; u < 5; ++u) {
            ull* ap = (ull*)(SA + (ty + 16 * u) * PITCH);
#pragma unroll
            for (int v = 0; v < 3; ++v) ap[pv[v]] = acc[u][v];
        }
    }
    __syncthreads();

    // phase 1: T = A*G
    ull accT[5][3];
#pragma unroll
    for (int u = 0; u < 5; ++u)
#pragma unroll
        for (int v = 0; v < 3; ++v) accT[u][v] = 0ull;
#pragma unroll 5
    for (int k = 0; k < DD; ++k) {
        const ull* gr = (const ull*)(SG + k * PITCH);
        ull b0 = gr[p0], b1 = gr[p1], b2 = gr[p2];
#pragma unroll
        for (int u = 0; u < 5; ++u) {
            ull ad = pack2(SA[(ty + 16 * u) * PITCH + k]);
            accT[u][0] = fma2(ad, b0, accT[u][0]);
            accT[u][1] = fma2(ad, b1, accT[u][1]);
            accT[u][2] = fma2(ad, b2, accT[u][2]);
        }
    }
    __syncthreads();

#pragma unroll
    for (int u = 0; u < 5; ++u) {
        ull* tp = (ull*)(ST + (ty + 16 * u) * PITCH);
#pragma unroll
        for (int v = 0; v < 3; ++v) tp[pv[v]] = accT[u][v];
    }
    for (int idx = tid; idx < DSQ; idx += 256) {
        int j = idx / DD, k = idx - j * DD;
        SW[k * PITCH + j] = Wv[idx];
    }
    __syncthreads();

    // phase 2: M = T*Wv^T
    {
        ull acc[5][3];
#pragma unroll
        for (int u = 0; u < 5; ++u)
#pragma unroll
            for (int v = 0; v < 3; ++v) acc[u][v] = 0ull;
#pragma unroll 5
        for (int k = 0; k < DD; ++k) {
            const ull* wr = (const ull*)(SW + k * PITCH);
            ull b0 = wr[p0], b1 = wr[p1], b2 = wr[p2];
#pragma unroll
            for (int u = 0; u < 5; ++u) {
                ull ad = pack2(ST[(ty + 16 * u) * PITCH + k]);
                acc[u][0] = fma2(ad, b0, acc[u][0]);
                acc[u][1] = fma2(ad, b1, acc[u][1]);
                acc[u][2] = fma2(ad, b2, acc[u][2]);
            }
        }
        float* Mb = g_M + (size_t)b * DSQ;
#pragma unroll
        for (int u = 0; u < 5; ++u) {
            int i = ty + 16 * u;
            if (i >= DD) continue;
#pragma unroll
            for (int v = 0; v < 3; ++v) {
                int j0 = 2 * pv[v];
                float lo, hi;
                unpack2(acc[u][v], lo, hi);
                if (j0     < DD) Mb[i * DD + j0]     = lo;
                if (j0 + 1 < DD) Mb[i * DD + j0 + 1] = hi;
            }
        }
    }
}

// ---------------------------------------------------------------------------
// Kernel 4: out_chunk = x_chunk * M_b, pair dimension = OUTPUT ROWS.
// a = natural x row-pair from transposed xsT[k][r]; b = pack2(M[k][j]) loaded
// one column at a time (2 live m-regs). smem 51 KB -> 4 blocks/SM.
// Epilogue staged via smem (reuses xsT) then coalesced STG.
// grid (16, 32), block 256.
// ---------------------------------------------------------------------------
__global__ void __launch_bounds__(256, 4) k_out(const float* __restrict__ x,
                                                float* __restrict__ out) {
    extern __shared__ __align__(16) float smo[];
    float* Ms  = smo;                 // 65*66
    float* xsT = smo + DD * 66;       // 65*130 transposed x; reused as osm[128*65]
    float* osm = xsT;

    const int b = blockIdx.y, c = blockIdx.x;
    const float* xp = x + ((size_t)b * NN + (size_t)c * OCH) * DD;
    float* op = out + ((size_t)b * NN + (size_t)c * OCH) * DD;
    const int tid = threadIdx.x;

    const float* Mg = g_M + (size_t)b * DSQ;
    for (int idx = tid; idx < DSQ; idx += 256) {
        int k = idx / DD, j = idx - k * DD;
        Ms[k * 66 + j] = Mg[idx];
    }
    for (int idx = tid; idx < OCH * DD; idx += 256) {
        int r = idx / DD, k = idx - r * DD;
        xsT[k * 130 + r] = xp[idx];
    }
    __syncthreads();

    const int ty = tid >> 4, tx = tid & 15;
    int jv[5];
#pragma unroll
    for (int v = 0; v < 5; ++v) {
        int j = ty + 16 * v;
        jv[v] = (j < DD) ? j : (DD - 1);   // clamp loads; stores guarded by real j
    }

    ull acc[4][5];
#pragma unroll
    for (int u = 0; u < 4; ++u)
#pragma unroll
        for (int v = 0; v < 5; ++v) acc[u][v] = 0ull;

    const ull* xu = (const ull*)xsT;   // pitch 65 ulls per k
#pragma unroll 5
    for (int k = 0; k < DD; ++k) {
        const ull* xk = xu + k * 65;
        ull a0 = xk[tx];
        ull a1 = xk[tx + 16];
        ull a2 = xk[tx + 32];
        ull a3 = xk[tx + 48];
        const float* mk = Ms + k * 66;
#pragma unroll
        for (int v = 0; v < 5; ++v) {
            ull m = pack2(mk[jv[v]]);
            acc[0][v] = fma2(a0, m, acc[0][v]);
            acc[1][v] = fma2(a1, m, acc[1][v]);
            acc[2][v] = fma2(a2, m, acc[2][v]);
            acc[3][v] = fma2(a3, m, acc[3][v]);
        }
    }

    __syncthreads();   // all xsT reads done before osm overwrite

#pragma unroll
    for (int u = 0; u < 4; ++u) {
        int r0 = 2 * (tx + 16 * u);
#pragma unroll
        for (int v = 0; v < 5; ++v) {
            int j = ty + 16 * v;
            if (j < DD) {
                float lo, hi;
                unpack2(acc[u][v], lo, hi);
                osm[r0 * DD + j]       = lo;
                osm[(r0 + 1) * DD + j] = hi;
            }
        }
    }
    __syncthreads();

    for (int idx = tid; idx < OCH * DD; idx += 256)
        op[idx] = osm[idx];
}

// ---------------------------------------------------------------------------
extern "C" void kernel_launch(void* const* d_in, const int* in_sizes, int n_in,
                              void* d_out, int out_size) {
    const float* x  = (const float*)d_in[0];   // [32, 2048, 65]
    const float* Wq = (const float*)d_in[1];   // [64, 65]
    const float* Wk = (const float*)d_in[2];   // [64, 65]
    const float* Wv = (const float*)d_in[3];   // [65, 65]
    float* out = (float*)d_out;                // [32, 2048, 65]

    const int smem_mid = (3 * ROWS80 + DD * PITCH) * 4;   // 82960 B
    const int smem_out = (DD * 66 + DD * 130) * 4;        // 50960 B
    cudaFuncSetAttribute(k_mid2, cudaFuncAttributeMaxDynamicSharedMemorySize, smem_mid);
    cudaFuncSetAttribute(k_out,  cudaFuncAttributeMaxDynamicSharedMemorySize, smem_out);

    k_gram<<<dim3(NGC, BB), 256>>>(x);
    k_reduce<<<dim3(17, BB), 256>>>();
    k_mid2<<<BB, 256, smem_mid>>>(Wq, Wk, Wv);
    k_out<<<dim3(NOC, BB), 256, smem_out>>>(x, out);
}